// round 3
// baseline (speedup 1.0000x reference)
#include <cuda_runtime.h>
#include <math.h>

// Problem constants
#define B      16
#define C      3
#define H      256
#define W      256
#define HW     65536      // 256*256
#define D      196608     // C*H*W
#define NEXP   4
#define TOPK   2
#define HID    64
#define FC     6

// ---------------- device scratch (no allocations allowed) ----------------
__device__ float g_refsum[B * C];   // per (b,c) sum over spatial of ref
__device__ float g_scale[B * C];    // 1 + prompt[b,c]
__device__ float g_logits[B * 8];   // [b][0..3]=clean, [4..7]=raw noise logit
__device__ float g_gate[B * 2];     // top-2 gate values per batch
__device__ int   g_eidx[B * 2];     // top-2 expert indices per batch

// ---------------- K1: sum ref over spatial per (b,c) ----------------
__global__ void k_refsum(const float* __restrict__ ref) {
    const float* p = ref + (size_t)blockIdx.x * HW;
    float s = 0.f;
    for (int i = threadIdx.x; i < HW; i += 256) s += p[i];
    __shared__ float sm[256];
    sm[threadIdx.x] = s;
    __syncthreads();
    for (int st = 128; st > 0; st >>= 1) {
        if (threadIdx.x < st) sm[threadIdx.x] += sm[threadIdx.x + st];
        __syncthreads();
    }
    if (threadIdx.x == 0) g_refsum[blockIdx.x] = sm[0];
}

// ---------------- K2: DC-bin prompt math (whole FFT chain collapsed) -----
// spatial.mean(2,3) of irfft2(Z, ortho) == Re(Z[0,0]) / 256, and the
// channel MLPs are pointwise in frequency -> only DC bin is needed.
__global__ void k_prompt(const float* __restrict__ mod_w1,
                         const float* __restrict__ mod_b1,
                         const float* __restrict__ mod_w2,
                         const float* __restrict__ mod_b2,
                         const float* __restrict__ enh_w,
                         const float* __restrict__ enh_b,
                         const float* __restrict__ fre_prompt) {
    int b = threadIdx.x;
    if (b >= B) return;
    // DC of rfft2(ref, ortho) = sum/256, imag = 0
    float s[3];
#pragma unroll
    for (int c = 0; c < 3; c++) s[c] = g_refsum[b * 3 + c] * (1.f / 256.f);
    float p[12];
#pragma unroll
    for (int i = 0; i < 12; i++) {
        int ci = (i < 6) ? i : i - 6;
        p[i] = (ci < 3) ? s[ci] : 0.f;
    }
    float m1[6];
#pragma unroll
    for (int o = 0; o < 6; o++) {
        float a = mod_b1[o];
#pragma unroll
        for (int i = 0; i < 12; i++) a += mod_w1[o * 12 + i] * p[i];
        m1[o] = fmaxf(a, 0.f);
    }
    float m2[6];
#pragma unroll
    for (int o = 0; o < 6; o++) {
        float a = mod_b2[o];
#pragma unroll
        for (int i = 0; i < 6; i++) a += mod_w2[o * 6 + i] * m1[i];
        m2[o] = a;
    }
    float ein[6];
#pragma unroll
    for (int c = 0; c < 6; c++) ein[c] = m2[c] * fre_prompt[c * (H * (W / 2 + 1))];
    float enh[6];
#pragma unroll
    for (int o = 0; o < 6; o++) {
        float a = enh_b[o];
#pragma unroll
        for (int i = 0; i < 6; i++) a += enh_w[o * 6 + i] * ein[i];
        enh[o] = fmaxf(a, 0.f);
    }
    // spatial mean = enh[c]/256 (c = 0..2), softmax over channel
    float v0 = enh[0] * (1.f / 256.f);
    float v1 = enh[1] * (1.f / 256.f);
    float v2 = enh[2] * (1.f / 256.f);
    float mx = fmaxf(v0, fmaxf(v1, v2));
    float e0 = expf(v0 - mx), e1 = expf(v1 - mx), e2 = expf(v2 - mx);
    float inv = 1.f / (e0 + e1 + e2);
    g_scale[b * 3 + 0] = 1.f + e0 * inv;
    g_scale[b * 3 + 1] = 1.f + e1 * inv;
    g_scale[b * 3 + 2] = 1.f + e2 * inv;
}

// ---------------- K3: gating matvecs (clean logits + raw noise logits) ---
__global__ void k_gate_dots(const float* __restrict__ x,
                            const float* __restrict__ w_gate,
                            const float* __restrict__ w_noise) {
    const int b = blockIdx.x;
    const int tid = threadIdx.x;
    const float sc0 = g_scale[b * 3 + 0];
    const float sc1 = g_scale[b * 3 + 1];
    const float sc2 = g_scale[b * 3 + 2];
    const float* xb = x + (size_t)b * D;
    float a[8] = {0, 0, 0, 0, 0, 0, 0, 0};
    const float4* wg4 = (const float4*)w_gate;
    const float4* wn4 = (const float4*)w_noise;
    for (int i = tid; i < D; i += 512) {
        float sc = (i < HW) ? sc0 : ((i < 2 * HW) ? sc1 : sc2);
        float xv = xb[i] * sc;
        float4 wg = wg4[i];
        float4 wn = wn4[i];
        a[0] += xv * wg.x; a[1] += xv * wg.y; a[2] += xv * wg.z; a[3] += xv * wg.w;
        a[4] += xv * wn.x; a[5] += xv * wn.y; a[6] += xv * wn.z; a[7] += xv * wn.w;
    }
    __shared__ float sm[512 * 8];
#pragma unroll
    for (int k = 0; k < 8; k++) sm[tid * 8 + k] = a[k];
    __syncthreads();
    for (int st = 256; st > 0; st >>= 1) {
        if (tid < st) {
#pragma unroll
            for (int k = 0; k < 8; k++) sm[tid * 8 + k] += sm[(tid + st) * 8 + k];
        }
        __syncthreads();
    }
    if (tid == 0) {
#pragma unroll
        for (int k = 0; k < 8; k++) g_logits[b * 8 + k] = sm[k];
    }
}

// ---------------- K4: noisy top-k gating + load-balance loss -------------
__device__ __forceinline__ float cv2_4(float a, float b, float c, float d) {
    float m = (a + b + c + d) * 0.25f;
    float va = a - m, vb = b - m, vc = c - m, vd = d - m;
    float var = (va * va + vb * vb + vc * vc + vd * vd) * (1.f / 3.f); // ddof=1
    return var / (m * m + 1e-10f);
}

__global__ void k_finalize(const float* __restrict__ noise,
                           float* __restrict__ out, int out_size) {
    const int lane = threadIdx.x; // 32 threads, lanes 0..15 handle batches
    float prob[4] = {0, 0, 0, 0};
    float gates[4] = {0, 0, 0, 0};
    if (lane < B) {
        const int b = lane;
        float clean[4], stdv[4], noisy[4];
#pragma unroll
        for (int e = 0; e < 4; e++) {
            clean[e] = g_logits[b * 8 + e];
            float z = g_logits[b * 8 + 4 + e];
            float sp = (z > 0.f) ? (z + log1pf(expf(-z))) : log1pf(expf(z));
            stdv[e] = sp + 0.01f; // + NOISE_EPS
            noisy[e] = clean[e] + noise[b * 4 + e] * stdv[e];
        }
        // top-3 of 4, descending, lower index wins ties (strict >)
        float v[4] = {noisy[0], noisy[1], noisy[2], noisy[3]};
        int idx[4] = {0, 1, 2, 3};
#pragma unroll
        for (int s = 0; s < 3; s++) {
            int m = s;
#pragma unroll
            for (int j = s + 1; j < 4; j++)
                if (v[j] > v[m]) m = j;
            float tv = v[s]; v[s] = v[m]; v[m] = tv;
            int ti = idx[s]; idx[s] = idx[m]; idx[m] = ti;
        }
        float t1 = v[1], t2 = v[2];
        // softmax over top-2
        float mx = fmaxf(v[0], v[1]);
        float e0 = expf(v[0] - mx), e1 = expf(v[1] - mx);
        float inv = 1.f / (e0 + e1);
        float gA = e0 * inv, gB = e1 * inv;
        gates[idx[0]] = gA;
        gates[idx[1]] = gB;
        g_eidx[b * 2 + 0] = idx[0];
        g_eidx[b * 2 + 1] = idx[1];
        g_gate[b * 2 + 0] = gA;
        g_gate[b * 2 + 1] = gB;
        // load probabilities (normal CDF)
#pragma unroll
        for (int e = 0; e < 4; e++) {
            float thr = (noisy[e] > t2) ? t2 : t1;
            float z = (clean[e] - thr) / stdv[e];
            prob[e] = 0.5f * erfcf(-z * 0.70710678118654752f);
        }
    }
    // warp reduce over the 16 batch lanes (others hold zeros)
#pragma unroll
    for (int off = 16; off > 0; off >>= 1) {
#pragma unroll
        for (int e = 0; e < 4; e++) {
            prob[e]  += __shfl_down_sync(0xffffffffu, prob[e], off);
            gates[e] += __shfl_down_sync(0xffffffffu, gates[e], off);
        }
    }
    if (lane == 0) {
        float loss = (cv2_4(gates[0], gates[1], gates[2], gates[3]) +
                      cv2_4(prob[0], prob[1], prob[2], prob[3])) * 0.01f;
        if (out_size > B * HW) out[B * HW] = loss;
    }
}

// ---------------- K5: fused sparse expert convs ---------------------------
// One block = one (batch, 16x16 output tile). Loops the batch's 2 selected
// experts; conv1(3x3, C=3->64)+ReLU kept in smem in 16-channel chunks;
// conv2(3x3, 64->1) accumulates from smem. Intermediate h never hits HBM.
//
// Boundary fix: conv2's SAME padding requires h == 0 OUTSIDE the 256x256
// image. The h-halo computed from zero-padded x is NOT zero there, so
// boundary tiles explicitly zero h at out-of-image global coordinates.
#define TDIM 16
#define XW   21   // padded x row stride (odd -> conflict-free)
#define HWID 19   // padded h row stride (odd)

__global__ void __launch_bounds__(256, 4)
k_expert(const float* __restrict__ x,
         const float* __restrict__ ew1, const float* __restrict__ eb1,
         const float* __restrict__ ew2, const float* __restrict__ eb2,
         float* __restrict__ out) {
    const int b = blockIdx.z, tY = blockIdx.y, tX = blockIdx.x;
    const int tid = threadIdx.x;

    __shared__ float xs[3 * 20 * XW];     // x tile + halo2 (20x20 valid)
    __shared__ float hs[16 * 18 * HWID];  // 16-channel h chunk (18x18 valid)
    __shared__ float w1s[16 * 27];
    __shared__ float w2s[16 * 9];
    __shared__ float b1s[16];

    // load x tile (shared by both expert slots)
    const int gy0 = tY * TDIM - 2, gx0 = tX * TDIM - 2;
    for (int i = tid; i < 3 * 20 * 20; i += 256) {
        int c = i / 400, r = (i / 20) % 20, col = i % 20;
        int gy = gy0 + r, gx = gx0 + col;
        float v = 0.f;
        if ((unsigned)gy < 256u && (unsigned)gx < 256u)
            v = x[((size_t)(b * 3 + c) << 16) + (gy << 8) + gx];
        xs[(c * 20 + r) * XW + col] = v;
    }

    const int oy = tid >> 4, ox = tid & 15;
    // interior tiles: entire 18x18 h patch lies inside the image
    const bool interior = (tY > 0) && (tY < H / TDIM - 1) &&
                          (tX > 0) && (tX < W / TDIM - 1);
    float yacc = 0.f;

    for (int slot = 0; slot < 2; slot++) {
        const int e = g_eidx[b * 2 + slot];
        const float g = g_gate[b * 2 + slot];
        const float* W1 = ew1 + e * (HID * 27);
        const float* W2 = ew2 + e * (HID * 9);
        const float* B1 = eb1 + e * HID;
        float part = 0.f;

        for (int ch = 0; ch < 4; ch++) {
            __syncthreads(); // prior chunk's reads done; also covers xs fill
            for (int i = tid; i < 432; i += 256) w1s[i] = W1[ch * 432 + i];
            for (int i = tid; i < 144; i += 256) w2s[i] = W2[ch * 144 + i];
            if (tid < 16) b1s[tid] = B1[ch * 16 + tid];
            __syncthreads();

            // conv1 + ReLU: tasks = 16 oc x 18 rows, sliding window over x
            for (int t = tid; t < 16 * 18; t += 256) {
                const int ocl = t / 18, yy = t % 18;
                float acc[18];
                const float bias = b1s[ocl];
#pragma unroll
                for (int j = 0; j < 18; j++) acc[j] = bias;
#pragma unroll
                for (int ic = 0; ic < 3; ic++) {
#pragma unroll
                    for (int ky = 0; ky < 3; ky++) {
                        const float* row = &xs[(ic * 20 + yy + ky) * XW];
                        const float* wp = &w1s[ocl * 27 + ic * 9 + ky * 3];
                        const float wa = wp[0], wb = wp[1], wc = wp[2];
                        float r0 = row[0], r1 = row[1];
#pragma unroll
                        for (int j = 0; j < 18; j++) {
                            float r2 = row[j + 2];
                            acc[j] += r0 * wa + r1 * wb + r2 * wc;
                            r0 = r1; r1 = r2;
                        }
                    }
                }
                float* hrow = &hs[(ocl * 18 + yy) * HWID];
                if (interior) {
#pragma unroll
                    for (int j = 0; j < 18; j++) hrow[j] = fmaxf(acc[j], 0.f);
                } else {
                    // conv2 SAME padding: h == 0 outside the image
                    const bool rowok = (unsigned)(tY * TDIM + yy - 1) < (unsigned)H;
#pragma unroll
                    for (int j = 0; j < 18; j++) {
                        const bool ok = rowok &&
                            (unsigned)(tX * TDIM + j - 1) < (unsigned)W;
                        hrow[j] = ok ? fmaxf(acc[j], 0.f) : 0.f;
                    }
                }
            }
            __syncthreads();

            // conv2 partial: one output per thread
#pragma unroll 4
            for (int icl = 0; icl < 16; icl++) {
                const float* hp = &hs[(icl * 18 + oy) * HWID + ox];
                const float* wp = &w2s[icl * 9];
                part += hp[0]        * wp[0] + hp[1]        * wp[1] + hp[2]        * wp[2]
                      + hp[HWID]     * wp[3] + hp[HWID + 1] * wp[4] + hp[HWID + 2] * wp[5]
                      + hp[2 * HWID] * wp[6] + hp[2*HWID+1] * wp[7] + hp[2*HWID+2] * wp[8];
            }
        }
        yacc += g * (part + eb2[e]);
    }

    out[((size_t)b << 16) + ((tY * TDIM + oy) << 8) + (tX * TDIM + ox)] = yacc;
}

// ---------------- launch ---------------------------------------------------
extern "C" void kernel_launch(void* const* d_in, const int* in_sizes, int n_in,
                              void* d_out, int out_size) {
    const float* x          = (const float*)d_in[0];
    const float* ref        = (const float*)d_in[1];
    const float* noise      = (const float*)d_in[2];
    const float* mod_w1     = (const float*)d_in[3];
    const float* mod_b1     = (const float*)d_in[4];
    const float* mod_w2     = (const float*)d_in[5];
    const float* mod_b2     = (const float*)d_in[6];
    const float* enh_w      = (const float*)d_in[7];
    const float* enh_b      = (const float*)d_in[8];
    const float* fre_prompt = (const float*)d_in[9];
    const float* w_gate     = (const float*)d_in[10];
    const float* w_noise    = (const float*)d_in[11];
    const float* ew1        = (const float*)d_in[12];
    const float* eb1        = (const float*)d_in[13];
    const float* ew2        = (const float*)d_in[14];
    const float* eb2        = (const float*)d_in[15];
    float* out = (float*)d_out;

    k_refsum<<<B * C, 256>>>(ref);
    k_prompt<<<1, 32>>>(mod_w1, mod_b1, mod_w2, mod_b2, enh_w, enh_b, fre_prompt);
    k_gate_dots<<<B, 512>>>(x, w_gate, w_noise);
    k_finalize<<<1, 32>>>(noise, out, out_size);
    k_expert<<<dim3(W / TDIM, H / TDIM, B), 256>>>(x, ew1, eb1, ew2, eb2, out);
}

// round 4
// speedup vs baseline: 1.3579x; 1.3579x over previous
#include <cuda_runtime.h>
#include <math.h>

// Problem constants
#define B      16
#define C      3
#define H      256
#define W      256
#define HW     65536      // 256*256
#define D      196608     // C*H*W
#define NEXP   4
#define TOPK   2
#define HID    64
#define FC     6

// ---------------- device scratch (no allocations allowed) ----------------
__device__ float g_refsum[B * C];   // per (b,c) sum over spatial of ref
__device__ float g_scale[B * C];    // 1 + prompt[b,c]
__device__ float g_logits[B * 8];   // [b][0..3]=clean, [4..7]=raw noise logit
__device__ float g_gate[B * 2];     // top-2 gate values per batch
__device__ int   g_eidx[B * 2];     // top-2 expert indices per batch

// ---------------- K1: sum ref over spatial per (b,c) ----------------
__global__ void k_refsum(const float* __restrict__ ref) {
    const float* p = ref + (size_t)blockIdx.x * HW;
    float s = 0.f;
    for (int i = threadIdx.x; i < HW; i += 256) s += p[i];
    __shared__ float sm[256];
    sm[threadIdx.x] = s;
    __syncthreads();
    for (int st = 128; st > 0; st >>= 1) {
        if (threadIdx.x < st) sm[threadIdx.x] += sm[threadIdx.x + st];
        __syncthreads();
    }
    if (threadIdx.x == 0) g_refsum[blockIdx.x] = sm[0];
}

// ---------------- K2: DC-bin prompt math (whole FFT chain collapsed) -----
__global__ void k_prompt(const float* __restrict__ mod_w1,
                         const float* __restrict__ mod_b1,
                         const float* __restrict__ mod_w2,
                         const float* __restrict__ mod_b2,
                         const float* __restrict__ enh_w,
                         const float* __restrict__ enh_b,
                         const float* __restrict__ fre_prompt) {
    int b = threadIdx.x;
    if (b >= B) return;
    float s[3];
#pragma unroll
    for (int c = 0; c < 3; c++) s[c] = g_refsum[b * 3 + c] * (1.f / 256.f);
    float p[12];
#pragma unroll
    for (int i = 0; i < 12; i++) {
        int ci = (i < 6) ? i : i - 6;
        p[i] = (ci < 3) ? s[ci] : 0.f;
    }
    float m1[6];
#pragma unroll
    for (int o = 0; o < 6; o++) {
        float a = mod_b1[o];
#pragma unroll
        for (int i = 0; i < 12; i++) a += mod_w1[o * 12 + i] * p[i];
        m1[o] = fmaxf(a, 0.f);
    }
    float m2[6];
#pragma unroll
    for (int o = 0; o < 6; o++) {
        float a = mod_b2[o];
#pragma unroll
        for (int i = 0; i < 6; i++) a += mod_w2[o * 6 + i] * m1[i];
        m2[o] = a;
    }
    float ein[6];
#pragma unroll
    for (int c = 0; c < 6; c++) ein[c] = m2[c] * fre_prompt[c * (H * (W / 2 + 1))];
    float enh[6];
#pragma unroll
    for (int o = 0; o < 6; o++) {
        float a = enh_b[o];
#pragma unroll
        for (int i = 0; i < 6; i++) a += enh_w[o * 6 + i] * ein[i];
        enh[o] = fmaxf(a, 0.f);
    }
    float v0 = enh[0] * (1.f / 256.f);
    float v1 = enh[1] * (1.f / 256.f);
    float v2 = enh[2] * (1.f / 256.f);
    float mx = fmaxf(v0, fmaxf(v1, v2));
    float e0 = expf(v0 - mx), e1 = expf(v1 - mx), e2 = expf(v2 - mx);
    float inv = 1.f / (e0 + e1 + e2);
    g_scale[b * 3 + 0] = 1.f + e0 * inv;
    g_scale[b * 3 + 1] = 1.f + e1 * inv;
    g_scale[b * 3 + 2] = 1.f + e2 * inv;
}

// ---------------- K3: gating matvecs ----------------
__global__ void k_gate_dots(const float* __restrict__ x,
                            const float* __restrict__ w_gate,
                            const float* __restrict__ w_noise) {
    const int b = blockIdx.x;
    const int tid = threadIdx.x;
    const float sc0 = g_scale[b * 3 + 0];
    const float sc1 = g_scale[b * 3 + 1];
    const float sc2 = g_scale[b * 3 + 2];
    const float* xb = x + (size_t)b * D;
    float a[8] = {0, 0, 0, 0, 0, 0, 0, 0};
    const float4* wg4 = (const float4*)w_gate;
    const float4* wn4 = (const float4*)w_noise;
    for (int i = tid; i < D; i += 512) {
        float sc = (i < HW) ? sc0 : ((i < 2 * HW) ? sc1 : sc2);
        float xv = xb[i] * sc;
        float4 wg = wg4[i];
        float4 wn = wn4[i];
        a[0] += xv * wg.x; a[1] += xv * wg.y; a[2] += xv * wg.z; a[3] += xv * wg.w;
        a[4] += xv * wn.x; a[5] += xv * wn.y; a[6] += xv * wn.z; a[7] += xv * wn.w;
    }
    __shared__ float sm[512 * 8];
#pragma unroll
    for (int k = 0; k < 8; k++) sm[tid * 8 + k] = a[k];
    __syncthreads();
    for (int st = 256; st > 0; st >>= 1) {
        if (tid < st) {
#pragma unroll
            for (int k = 0; k < 8; k++) sm[tid * 8 + k] += sm[(tid + st) * 8 + k];
        }
        __syncthreads();
    }
    if (tid == 0) {
#pragma unroll
        for (int k = 0; k < 8; k++) g_logits[b * 8 + k] = sm[k];
    }
}

// ---------------- K4: noisy top-k gating + load-balance loss -------------
__device__ __forceinline__ float cv2_4(float a, float b, float c, float d) {
    float m = (a + b + c + d) * 0.25f;
    float va = a - m, vb = b - m, vc = c - m, vd = d - m;
    float var = (va * va + vb * vb + vc * vc + vd * vd) * (1.f / 3.f);
    return var / (m * m + 1e-10f);
}

__global__ void k_finalize(const float* __restrict__ noise,
                           float* __restrict__ out, int out_size) {
    const int lane = threadIdx.x;
    float prob[4] = {0, 0, 0, 0};
    float gates[4] = {0, 0, 0, 0};
    if (lane < B) {
        const int b = lane;
        float clean[4], stdv[4], noisy[4];
#pragma unroll
        for (int e = 0; e < 4; e++) {
            clean[e] = g_logits[b * 8 + e];
            float z = g_logits[b * 8 + 4 + e];
            float sp = (z > 0.f) ? (z + log1pf(expf(-z))) : log1pf(expf(z));
            stdv[e] = sp + 0.01f;
            noisy[e] = clean[e] + noise[b * 4 + e] * stdv[e];
        }
        float v[4] = {noisy[0], noisy[1], noisy[2], noisy[3]};
        int idx[4] = {0, 1, 2, 3};
#pragma unroll
        for (int s = 0; s < 3; s++) {
            int m = s;
#pragma unroll
            for (int j = s + 1; j < 4; j++)
                if (v[j] > v[m]) m = j;
            float tv = v[s]; v[s] = v[m]; v[m] = tv;
            int ti = idx[s]; idx[s] = idx[m]; idx[m] = ti;
        }
        float t1 = v[1], t2 = v[2];
        float mx = fmaxf(v[0], v[1]);
        float e0 = expf(v[0] - mx), e1 = expf(v[1] - mx);
        float inv = 1.f / (e0 + e1);
        float gA = e0 * inv, gB = e1 * inv;
        gates[idx[0]] = gA;
        gates[idx[1]] = gB;
        g_eidx[b * 2 + 0] = idx[0];
        g_eidx[b * 2 + 1] = idx[1];
        g_gate[b * 2 + 0] = gA;
        g_gate[b * 2 + 1] = gB;
#pragma unroll
        for (int e = 0; e < 4; e++) {
            float thr = (noisy[e] > t2) ? t2 : t1;
            float z = (clean[e] - thr) / stdv[e];
            prob[e] = 0.5f * erfcf(-z * 0.70710678118654752f);
        }
    }
#pragma unroll
    for (int off = 16; off > 0; off >>= 1) {
#pragma unroll
        for (int e = 0; e < 4; e++) {
            prob[e]  += __shfl_down_sync(0xffffffffu, prob[e], off);
            gates[e] += __shfl_down_sync(0xffffffffu, gates[e], off);
        }
    }
    if (lane == 0) {
        float loss = (cv2_4(gates[0], gates[1], gates[2], gates[3]) +
                      cv2_4(prob[0], prob[1], prob[2], prob[3])) * 0.01f;
        if (out_size > B * HW) out[B * HW] = loss;
    }
}

// ---------------- K5: fused sparse expert convs ---------------------------
// One block = one (batch, 16x16 output tile). conv1 (3->64) + ReLU into smem
// in 16-channel chunks. conv2 (64->1) restructured as 256 row-sliding tasks
// (y, icl): each computes a 16-wide partial row with a sliding window
// (54 h-LDS for 144 FMA instead of 288 LDS/144 FMA), accumulated into a
// shared part[icl][y][x] buffer. Both experts accumulate into the SAME part
// buffer with gate-pre-scaled w2 (conv2 linear in w2); one reduce at the end.
#define TDIM 16
#define XW   21    // padded x row stride (odd -> conflict-free)
#define HWID 19    // padded h row stride (odd)
#define PICL 274   // part icl-stride: even-residue banks x odd y-offset => conflict-free

__global__ void __launch_bounds__(256, 4)
k_expert(const float* __restrict__ x,
         const float* __restrict__ ew1, const float* __restrict__ eb1,
         const float* __restrict__ ew2, const float* __restrict__ eb2,
         float* __restrict__ out) {
    const int b = blockIdx.z, tY = blockIdx.y, tX = blockIdx.x;
    const int tid = threadIdx.x;

    __shared__ float xs[3 * 20 * XW];     // 5040 f
    __shared__ float hs[16 * 18 * HWID];  // 5472 f
    __shared__ float part[16 * PICL];     // 4384 f : part[icl*PICL + y*17 + x]
    __shared__ float w1s[16 * 27];
    __shared__ float w2s[16 * 9];
    __shared__ float b1s[16];

    // zero part accumulator
    for (int i = tid; i < 16 * PICL; i += 256) part[i] = 0.f;

    // load x tile (+halo 2), shared by both experts
    const int gy0 = tY * TDIM - 2, gx0 = tX * TDIM - 2;
    for (int i = tid; i < 3 * 20 * 20; i += 256) {
        int c = i / 400, r = (i / 20) % 20, col = i % 20;
        int gy = gy0 + r, gx = gx0 + col;
        float v = 0.f;
        if ((unsigned)gy < 256u && (unsigned)gx < 256u)
            v = x[((size_t)(b * 3 + c) << 16) + (gy << 8) + gx];
        xs[(c * 20 + r) * XW + col] = v;
    }

    const bool interior = (tY > 0) && (tY < H / TDIM - 1) &&
                          (tX > 0) && (tX < W / TDIM - 1);

    // conv2 task decomposition (fixed per thread)
    const int cy   = tid >> 4;   // output row 0..15
    const int cicl = tid & 15;   // local channel 0..15

    for (int slot = 0; slot < 2; slot++) {
        const int e = g_eidx[b * 2 + slot];
        const float g = g_gate[b * 2 + slot];
        const float* W1 = ew1 + e * (HID * 27);
        const float* W2 = ew2 + e * (HID * 9);
        const float* B1 = eb1 + e * HID;

        for (int ch = 0; ch < 4; ch++) {
            __syncthreads(); // prior-chunk conv2 reads done (also covers xs/part init)
            for (int i = tid; i < 432; i += 256) w1s[i] = W1[ch * 432 + i];
            // pre-scale conv2 weights by gate -> single shared part buffer
            for (int i = tid; i < 144; i += 256) w2s[i] = g * W2[ch * 144 + i];
            if (tid < 16) b1s[tid] = B1[ch * 16 + tid];
            __syncthreads();

            // conv1 + ReLU: 288 tasks = 16 oc x 18 rows, sliding window
            for (int t = tid; t < 16 * 18; t += 256) {
                const int ocl = t / 18, yy = t % 18;
                float acc[18];
                const float bias = b1s[ocl];
#pragma unroll
                for (int j = 0; j < 18; j++) acc[j] = bias;
#pragma unroll
                for (int ic = 0; ic < 3; ic++) {
#pragma unroll
                    for (int ky = 0; ky < 3; ky++) {
                        const float* row = &xs[(ic * 20 + yy + ky) * XW];
                        const float* wp = &w1s[ocl * 27 + ic * 9 + ky * 3];
                        const float wa = wp[0], wb = wp[1], wc = wp[2];
                        float r0 = row[0], r1 = row[1];
#pragma unroll
                        for (int j = 0; j < 18; j++) {
                            float r2 = row[j + 2];
                            acc[j] += r0 * wa + r1 * wb + r2 * wc;
                            r0 = r1; r1 = r2;
                        }
                    }
                }
                float* hrow = &hs[(ocl * 18 + yy) * HWID];
                if (interior) {
#pragma unroll
                    for (int j = 0; j < 18; j++) hrow[j] = fmaxf(acc[j], 0.f);
                } else {
                    // conv2 SAME padding: h == 0 outside the image
                    const bool rowok = (unsigned)(tY * TDIM + yy - 1) < (unsigned)H;
#pragma unroll
                    for (int j = 0; j < 18; j++) {
                        const bool ok = rowok &&
                            (unsigned)(tX * TDIM + j - 1) < (unsigned)W;
                        hrow[j] = ok ? fmaxf(acc[j], 0.f) : 0.f;
                    }
                }
            }
            __syncthreads();

            // conv2 partial row: task (cy, cicl), sliding window over 3 h rows
            {
                float acc2[16];
#pragma unroll
                for (int j = 0; j < 16; j++) acc2[j] = 0.f;
                const float* wp = &w2s[cicl * 9];
#pragma unroll
                for (int ky = 0; ky < 3; ky++) {
                    const float* row = &hs[(cicl * 18 + cy + ky) * HWID];
                    const float wa = wp[ky * 3], wb = wp[ky * 3 + 1], wc = wp[ky * 3 + 2];
                    float r0 = row[0], r1 = row[1];
#pragma unroll
                    for (int j = 0; j < 16; j++) {
                        float r2 = row[j + 2];
                        acc2[j] += r0 * wa + r1 * wb + r2 * wc;
                        r0 = r1; r1 = r2;
                    }
                }
                float* pp = &part[cicl * PICL + cy * 17];
#pragma unroll
                for (int j = 0; j < 16; j++) pp[j] += acc2[j];
            }
        }
    }

    __syncthreads(); // all part accumulation done

    // final reduce over 16 local channels + gate-weighted conv2 biases
    const int oy = tid >> 4, ox = tid & 15;
    float yacc = 0.f;
#pragma unroll
    for (int icl = 0; icl < 16; icl++)
        yacc += part[icl * PICL + oy * 17 + ox];
    {
        const int e0 = g_eidx[b * 2 + 0], e1 = g_eidx[b * 2 + 1];
        yacc += g_gate[b * 2 + 0] * eb2[e0] + g_gate[b * 2 + 1] * eb2[e1];
    }

    out[((size_t)b << 16) + ((tY * TDIM + oy) << 8) + (tX * TDIM + ox)] = yacc;
}

// ---------------- launch ---------------------------------------------------
extern "C" void kernel_launch(void* const* d_in, const int* in_sizes, int n_in,
                              void* d_out, int out_size) {
    const float* x          = (const float*)d_in[0];
    const float* ref        = (const float*)d_in[1];
    const float* noise      = (const float*)d_in[2];
    const float* mod_w1     = (const float*)d_in[3];
    const float* mod_b1     = (const float*)d_in[4];
    const float* mod_w2     = (const float*)d_in[5];
    const float* mod_b2     = (const float*)d_in[6];
    const float* enh_w      = (const float*)d_in[7];
    const float* enh_b      = (const float*)d_in[8];
    const float* fre_prompt = (const float*)d_in[9];
    const float* w_gate     = (const float*)d_in[10];
    const float* w_noise    = (const float*)d_in[11];
    const float* ew1        = (const float*)d_in[12];
    const float* eb1        = (const float*)d_in[13];
    const float* ew2        = (const float*)d_in[14];
    const float* eb2        = (const float*)d_in[15];
    float* out = (float*)d_out;

    k_refsum<<<B * C, 256>>>(ref);
    k_prompt<<<1, 32>>>(mod_w1, mod_b1, mod_w2, mod_b2, enh_w, enh_b, fre_prompt);
    k_gate_dots<<<B, 512>>>(x, w_gate, w_noise);
    k_finalize<<<1, 32>>>(noise, out, out_size);
    k_expert<<<dim3(W / TDIM, H / TDIM, B), 256>>>(x, ew1, eb1, ew2, eb2, out);
}